// round 13
// baseline (speedup 1.0000x reference)
#include <cuda_runtime.h>
#include <cuda_fp16.h>
#include <cstdint>

#define Bn 16
#define Dn 1024
#define Qn 128
#define Hn 1024
#define NEGINF (-1e30f)

// ---------------- scratch (device globals; no allocations) ----------------
__device__ float g_S  [Bn*Dn*Qn];   // raw scores [b][d][q]
__device__ float g_P  [Bn*Dn*Qn];   // S_d2q      [b][d][q]
__device__ float g_P2t[Bn*Qn*Dn];   // S_q2d^T    [b][q][d]
__device__ float g_Tt [Bn*Hn*Qn];   // T^T        [b][h][q]
__device__ float g_sd [Bn*Dn];
__device__ float g_sq [Bn*Qn];

// ---------------- helpers ----------------
__device__ __forceinline__ uint32_t smem_u32(const void* p){
    uint32_t a;
    asm("{ .reg .u64 t; cvta.to.shared.u64 t, %1; cvt.u32.u64 %0, t; }" : "=r"(a) : "l"(p));
    return a;
}
__device__ __forceinline__ void ldm4(uint32_t r[4], uint32_t addr){
    asm volatile("ldmatrix.sync.aligned.m8n8.x4.shared.b16 {%0,%1,%2,%3},[%4];"
        : "=r"(r[0]),"=r"(r[1]),"=r"(r[2]),"=r"(r[3]) : "r"(addr));
}
__device__ __forceinline__ void mmah(float c[4], const uint32_t a[4], uint32_t b0, uint32_t b1){
    asm volatile("mma.sync.aligned.m16n8k16.row.col.f32.f16.f16.f32 "
        "{%0,%1,%2,%3},{%4,%5,%6,%7},{%8,%9},{%0,%1,%2,%3};"
        : "+f"(c[0]),"+f"(c[1]),"+f"(c[2]),"+f"(c[3])
        : "r"(a[0]),"r"(a[1]),"r"(a[2]),"r"(a[3]),"r"(b0),"r"(b1));
}
__device__ __forceinline__ uint32_t pk2h(float x0, float x1){
    __half2 h = __floats2half2_rn(x0, x1);
    return *(uint32_t*)&h;
}
__device__ __forceinline__ void split2h(float x0, float x1, uint32_t& hi, uint32_t& lo){
    __half h0 = __float2half_rn(x0), h1 = __float2half_rn(x1);
    float r0 = x0 - __half2float(h0), r1 = x1 - __half2float(h1);
    hi = (uint32_t)__half_as_ushort(h0) | ((uint32_t)__half_as_ushort(h1)<<16);
    lo = (uint32_t)__half_as_ushort(__float2half_rn(r0)) |
         ((uint32_t)__half_as_ushort(__float2half_rn(r1))<<16);
}

// smem tiles: fp16 [128 rows][32 k], row stride 40 fp16 (80 B). offsets:
#define T0 0
#define T1 10240
#define T2 20480
#define STG_OFF 30720          // fp32 staging [32][132] = 16896 B (staged kernels)
#define SMEM_DIRECT 30720
#define SMEM_STAGED (30720 + 16896)

// load 128x32 fp32 K-major tile into regs (4 float4/thread, 256 threads)
__device__ __forceinline__ void load4(const float* src, size_t ld, int tid, float4 v[4]){
    const float* p = src + (size_t)(tid>>1)*ld + (tid&1)*16;
#pragma unroll
    for (int j=0;j<4;j++) v[j] = *(const float4*)(p + j*4);
}
// split regs -> hi/lo fp16 tiles
__device__ __forceinline__ void store_split(const float4 v[4], char* sm, int hiOff, int loOff, int tid){
    uint32_t h[8], l[8];
#pragma unroll
    for (int j=0;j<4;j++){
        split2h(v[j].x,v[j].y,h[2*j],l[2*j]);
        split2h(v[j].z,v[j].w,h[2*j+1],l[2*j+1]);
    }
    const int off = (tid>>1)*80 + (tid&1)*32;
    *(uint4*)(sm + hiOff + off)      = make_uint4(h[0],h[1],h[2],h[3]);
    *(uint4*)(sm + hiOff + off + 16) = make_uint4(h[4],h[5],h[6],h[7]);
    *(uint4*)(sm + loOff + off)      = make_uint4(l[0],l[1],l[2],l[3]);
    *(uint4*)(sm + loOff + off + 16) = make_uint4(l[4],l[5],l[6],l[7]);
}
// single-rounded fp16 tile
__device__ __forceinline__ void store_single(const float4 v[4], char* sm, int off0, int tid){
    uint32_t h[8];
#pragma unroll
    for (int j=0;j<4;j++){
        h[2*j]   = pk2h(v[j].x,v[j].y);
        h[2*j+1] = pk2h(v[j].z,v[j].w);
    }
    const int off = (tid>>1)*80 + (tid&1)*32;
    *(uint4*)(sm + off0 + off)      = make_uint4(h[0],h[1],h[2],h[3]);
    *(uint4*)(sm + off0 + off + 16) = make_uint4(h[4],h[5],h[6],h[7]);
}
// staged transpose path: gmem [32 k-rows][128 cols] -> regs -> stg -> fp16 tile[col][k]
__device__ __forceinline__ void load_stage(const float* src, size_t ld, int tid, float4 v[4]){
#pragma unroll
    for (int p=0;p<4;p++){
        const int idx = p*256 + tid;
        v[p] = *(const float4*)(src + (size_t)(idx>>5)*ld + (idx&31)*4);
    }
}
__device__ __forceinline__ void store_stage(const float4 v[4], float* stg, int tid){
#pragma unroll
    for (int p=0;p<4;p++){
        const int idx = p*256 + tid;
        *(float4*)(stg + (idx>>5)*132 + (idx&31)*4) = v[p];
    }
}
__device__ __forceinline__ void trans_single(const float* stg, char* sm, int off0, int tid){
    const int h = tid>>1, kb = (tid&1)*16;
#pragma unroll
    for (int j=0;j<8;j++){
        const int k = kb + 2*j;
        *(uint32_t*)(sm + off0 + h*80 + k*2) = pk2h(stg[k*132 + h], stg[(k+1)*132 + h]);
    }
}

// 2-pass MMA, A split (AH+AL), B single. warp tile 32x64, 8 warps -> 128x128.
__device__ __forceinline__ void mma_chunk_As(uint32_t AH, uint32_t AL, uint32_t B,
                                             float acc[16][4], int lane, int wm, int wn)
{
    const int r16 = lane & 15;
    const int c8  = (lane >> 4) * 8;
#pragma unroll
    for (int kk = 0; kk < 32; kk += 16){
        uint32_t Ah[2][4], Al[2][4];
#pragma unroll
        for (int mi = 0; mi < 2; ++mi){
            const uint32_t off = (uint32_t)((wm + mi*16 + r16)*80 + (kk + c8)*2);
            ldm4(Ah[mi], AH + off);
            ldm4(Al[mi], AL + off);
        }
#pragma unroll
        for (int g = 0; g < 4; ++g){
            const uint32_t off = (uint32_t)((wn + g*16 + r16)*80 + (kk + c8)*2);
            uint32_t b[4];
            ldm4(b, B + off);
#pragma unroll
            for (int mi = 0; mi < 2; ++mi){
                mmah(acc[mi*8+2*g],   Ah[mi], b[0], b[2]);
                mmah(acc[mi*8+2*g+1], Ah[mi], b[1], b[3]);
                mmah(acc[mi*8+2*g],   Al[mi], b[0], b[2]);
                mmah(acc[mi*8+2*g+1], Al[mi], b[1], b[3]);
            }
        }
    }
}
// 2-pass MMA, A single, B split (BH+BL).
__device__ __forceinline__ void mma_chunk_Bs(uint32_t A, uint32_t BH, uint32_t BL,
                                             float acc[16][4], int lane, int wm, int wn)
{
    const int r16 = lane & 15;
    const int c8  = (lane >> 4) * 8;
#pragma unroll
    for (int kk = 0; kk < 32; kk += 16){
        uint32_t Aa[2][4];
#pragma unroll
        for (int mi = 0; mi < 2; ++mi){
            const uint32_t off = (uint32_t)((wm + mi*16 + r16)*80 + (kk + c8)*2);
            ldm4(Aa[mi], A + off);
        }
#pragma unroll
        for (int g = 0; g < 4; ++g){
            const uint32_t off = (uint32_t)((wn + g*16 + r16)*80 + (kk + c8)*2);
            uint32_t bh[4], bl[4];
            ldm4(bh, BH + off);
            ldm4(bl, BL + off);
#pragma unroll
            for (int mi = 0; mi < 2; ++mi){
                mmah(acc[mi*8+2*g],   Aa[mi], bh[0], bh[2]);
                mmah(acc[mi*8+2*g+1], Aa[mi], bh[1], bh[3]);
                mmah(acc[mi*8+2*g],   Aa[mi], bl[0], bl[2]);
                mmah(acc[mi*8+2*g+1], Aa[mi], bl[1], bl[3]);
            }
        }
    }
}

// ---------------- K0: s_d and s_q row dots ----------------
__global__ void k0_rowdots(const float* __restrict__ Ud, const float* __restrict__ Uq,
                           const float* __restrict__ wc)
{
    const int warp = (blockIdx.x * blockDim.x + threadIdx.x) >> 5;
    const int lane = threadIdx.x & 31;
    const int nrows = Bn*Dn + Bn*Qn;
    if (warp >= nrows) return;
    const float* row; const float* w; float* outp;
    if (warp < Bn*Dn) { row = Ud + (size_t)warp * Hn; w = wc;      outp = &g_sd[warp]; }
    else { int r = warp - Bn*Dn; row = Uq + (size_t)r * Hn; w = wc + Hn; outp = &g_sq[r]; }
    float s = 0.f;
#pragma unroll
    for (int j = 0; j < Hn/128; ++j) {
        float4 a  = *(const float4*)(row + (j*32 + lane)*4);
        float4 ww = *(const float4*)(w   + (j*32 + lane)*4);
        s += a.x*ww.x + a.y*ww.y + a.z*ww.z + a.w*ww.w;
    }
#pragma unroll
    for (int o = 16; o; o >>= 1) s += __shfl_xor_sync(0xffffffffu, s, o);
    if (lane == 0) *outp = s;
}

// ---------------- K1: S = (Ud*w)@Uq^T + s_d + s_q + b ; fused row softmax ----------------
// grid (8, 16), 256 thr, dsmem 30720. A split (Wd), B single (Uq).
__global__ void __launch_bounds__(256)
k1_score(const float* __restrict__ Ud, const float* __restrict__ Uq,
         const float* __restrict__ wc, const float* __restrict__ wcb,
         const int* __restrict__ qmask, const int* __restrict__ dmask)
{
    extern __shared__ __align__(16) char sm[];
    const int tid = threadIdx.x, lane = tid&31, wid = tid>>5;
    const int b = blockIdx.y, m0 = blockIdx.x*128;
    const int wm = (wid&3)*32, wn = (wid>>2)*64;
    const uint32_t sb = smem_u32(sm);

    const float* Asrc = Ud + ((size_t)b*Dn + m0)*Hn;
    const float* Bsrc = Uq + (size_t)b*Qn*Hn;
    const float* wd = wc + 2*Hn;

    float acc[16][4];
#pragma unroll
    for (int i=0;i<16;i++){acc[i][0]=acc[i][1]=acc[i][2]=acc[i][3]=0.f;}

    float4 va[4], vb[4];
    load4(Asrc, Hn, tid, va);
    {   const float* wp = wd + (tid&1)*16;
#pragma unroll
        for (int j=0;j<4;j++){ float4 w=*(const float4*)(wp+j*4); va[j].x*=w.x; va[j].y*=w.y; va[j].z*=w.z; va[j].w*=w.w; } }
    load4(Bsrc, Hn, tid, vb);

    for (int kt=0; kt<32; ++kt){
        __syncthreads();
        store_split(va, sm, T0, T1, tid);
        store_single(vb, sm, T2, tid);
        if (kt < 31){
            load4(Asrc + (kt+1)*32, Hn, tid, va);
            const float* wp = wd + (kt+1)*32 + (tid&1)*16;
#pragma unroll
            for (int j=0;j<4;j++){ float4 w=*(const float4*)(wp+j*4); va[j].x*=w.x; va[j].y*=w.y; va[j].z*=w.z; va[j].w*=w.w; }
            load4(Bsrc + (kt+1)*32, Hn, tid, vb);
        }
        __syncthreads();
        mma_chunk_As(sb+T0, sb+T1, sb+T2, acc, lane, wm, wn);
    }
    __syncthreads();   // tiles free; epilogue reuses smem

    float* redm = (float*)sm;          // [128][2]
    float* reds = (float*)(sm+1024);   // [128][2]
    const float bias = wcb[0];
    const int qrow = lane>>2, qc = (lane&3)*2;
    const int wcol = wn>>6;

    float sqv[8][2]; int qmv[8][2];
#pragma unroll
    for (int ni=0;ni<8;ni++){
        const int q = wn + ni*8 + qc;
        const float2 s = *(const float2*)(g_sq + b*Qn + q);
        const int2 qq = *(const int2*)(qmask + b*Qn + q);
        sqv[ni][0]=s.x; sqv[ni][1]=s.y; qmv[ni][0]=qq.x; qmv[ni][1]=qq.y;
    }
    float sdv[2][2]; int dmv[2][2];
#pragma unroll
    for (int mi=0;mi<2;mi++)
#pragma unroll
        for (int h2=0;h2<2;h2++){
            const int m = m0 + wm + mi*16 + 8*h2 + qrow;
            sdv[mi][h2] = g_sd[b*Dn + m] + bias;
            dmv[mi][h2] = dmask[b*Dn + m];
        }

    float pmax[2][2] = {{-3.0e38f,-3.0e38f},{-3.0e38f,-3.0e38f}};
#pragma unroll
    for (int mi=0;mi<2;mi++)
#pragma unroll
    for (int ni=0;ni<8;ni++)
#pragma unroll
    for (int h2=0;h2<2;h2++){
        const int m = m0 + wm + mi*16 + 8*h2 + qrow;
        float s0 = acc[mi*8+ni][h2*2+0] + sdv[mi][h2] + sqv[ni][0];
        float s1 = acc[mi*8+ni][h2*2+1] + sdv[mi][h2] + sqv[ni][1];
        *(float2*)(g_S + ((size_t)b*Dn + m)*Qn + wn + ni*8 + qc) = make_float2(s0, s1);
        const float l0 = (dmv[mi][h2]>0 && qmv[ni][0]>0) ? s0 : NEGINF;
        const float l1 = (dmv[mi][h2]>0 && qmv[ni][1]>0) ? s1 : NEGINF;
        acc[mi*8+ni][h2*2+0] = l0; acc[mi*8+ni][h2*2+1] = l1;
        pmax[mi][h2] = fmaxf(pmax[mi][h2], fmaxf(l0, l1));
    }
#pragma unroll
    for (int mi=0;mi<2;mi++)
#pragma unroll
        for (int h2=0;h2<2;h2++){
            pmax[mi][h2] = fmaxf(pmax[mi][h2], __shfl_xor_sync(0xffffffffu, pmax[mi][h2], 1));
            pmax[mi][h2] = fmaxf(pmax[mi][h2], __shfl_xor_sync(0xffffffffu, pmax[mi][h2], 2));
        }
    if ((lane&3)==0){
#pragma unroll
        for (int mi=0;mi<2;mi++)
#pragma unroll
            for (int h2=0;h2<2;h2++)
                redm[(wm + mi*16 + 8*h2 + qrow)*2 + wcol] = pmax[mi][h2];
    }
    __syncthreads();
    float rmax[2][2], psum[2][2];
#pragma unroll
    for (int mi=0;mi<2;mi++)
#pragma unroll
        for (int h2=0;h2<2;h2++){
            const int rl = wm + mi*16 + 8*h2 + qrow;
            rmax[mi][h2] = fmaxf(redm[rl*2], redm[rl*2+1]);
            psum[mi][h2] = 0.f;
        }
#pragma unroll
    for (int mi=0;mi<2;mi++)
#pragma unroll
    for (int ni=0;ni<8;ni++)
#pragma unroll
    for (int h2=0;h2<2;h2++){
        const float e0 = __expf(acc[mi*8+ni][h2*2+0] - rmax[mi][h2]);
        const float e1 = __expf(acc[mi*8+ni][h2*2+1] - rmax[mi][h2]);
        acc[mi*8+ni][h2*2+0] = e0; acc[mi*8+ni][h2*2+1] = e1;
        psum[mi][h2] += e0 + e1;
    }
#pragma unroll
    for (int mi=0;mi<2;mi++)
#pragma unroll
        for (int h2=0;h2<2;h2++){
            psum[mi][h2] += __shfl_xor_sync(0xffffffffu, psum[mi][h2], 1);
            psum[mi][h2] += __shfl_xor_sync(0xffffffffu, psum[mi][h2], 2);
        }
    if ((lane&3)==0){
#pragma unroll
        for (int mi=0;mi<2;mi++)
#pragma unroll
            for (int h2=0;h2<2;h2++)
                reds[(wm + mi*16 + 8*h2 + qrow)*2 + wcol] = psum[mi][h2];
    }
    __syncthreads();
#pragma unroll
    for (int mi=0;mi<2;mi++)
#pragma unroll
    for (int h2=0;h2<2;h2++){
        const int rl = wm + mi*16 + 8*h2 + qrow;
        const float ssum = reds[rl*2] + reds[rl*2+1];
        const float inv = ssum > 0.f ? 1.f/ssum : 0.f;
        const int m = m0 + rl;
#pragma unroll
        for (int ni=0;ni<8;ni++){
            const float p0 = (dmv[mi][h2]>0 && qmv[ni][0]>0) ? acc[mi*8+ni][h2*2+0]*inv : 0.f;
            const float p1 = (dmv[mi][h2]>0 && qmv[ni][1]>0) ? acc[mi*8+ni][h2*2+1]*inv : 0.f;
            *(float2*)(g_P + ((size_t)b*Dn + m)*Qn + wn + ni*8 + qc) = make_float2(p0, p1);
        }
    }
}

// ---------------- K3: column softmax over d -> g_P2t (transposed out) ----------------
__global__ void __launch_bounds__(1024)
k3_colsoftmax(const int* __restrict__ qmask, const int* __restrict__ dmask)
{
    const int b  = blockIdx.y;
    const int tx = threadIdx.x, ty = threadIdx.y;
    const int q0 = blockIdx.x*32;
    const int q  = q0 + tx;
    __shared__ float red[32][33];
    __shared__ float trn[32][33];
    const int qm = qmask[b*Qn + q];
    float v[32];
    float mx = -3.0e38f;
#pragma unroll
    for (int j = 0; j < 32; ++j) {
        const int d = ty + j*32;
        const float s = g_S[((size_t)b*Dn + d)*Qn + q];
        const float l = (qm > 0 && dmask[b*Dn + d] > 0) ? s : NEGINF;
        v[j] = l; mx = fmaxf(mx, l);
    }
    red[ty][tx] = mx; __syncthreads();
#pragma unroll
    for (int off = 16; off; off >>= 1) {
        if (ty < off) red[ty][tx] = fmaxf(red[ty][tx], red[ty+off][tx]);
        __syncthreads();
    }
    mx = red[0][tx];
    __syncthreads();
    float se = 0.f;
#pragma unroll
    for (int j = 0; j < 32; ++j) { v[j] = __expf(v[j] - mx); se += v[j]; }
    red[ty][tx] = se; __syncthreads();
#pragma unroll
    for (int off = 16; off; off >>= 1) {
        if (ty < off) red[ty][tx] += red[ty+off][tx];
        __syncthreads();
    }
    const float inv = 1.f / red[0][tx];
    __syncthreads();
    for (int j = 0; j < 32; ++j) {
        const int d = ty + j*32;
        const float ind = (qm > 0 && dmask[b*Dn + d] > 0) ? 1.f : 0.f;
        trn[ty][tx] = v[j]*inv*ind;
        __syncthreads();
        g_P2t[((size_t)b*Qn + q0 + ty)*Dn + j*32 + tx] = trn[tx][ty];
        __syncthreads();
    }
}

// ---------------- K4 body: T^T[h][q] = sum_d Ud^T[h][d] * P2t[q][d] ----------------
__device__ __forceinline__ void k4_body(char* sm, const float* __restrict__ Ud, int bx)
{
    float* stg = (float*)(sm + STG_OFF);
    const int tid = threadIdx.x, lane = tid&31, wid = tid>>5;
    const int b = bx>>3, h0 = (bx&7)*128;
    const int wm = (wid&3)*32, wn = (wid>>2)*64;
    const uint32_t sb = smem_u32(sm);

    const float* Atsrc = Ud + (size_t)b*Dn*Hn + h0;    // rows d, cols h
    const float* Bsrc  = g_P2t + (size_t)b*Qn*Dn;      // [q][d]

    float acc[16][4];
#pragma unroll
    for (int i=0;i<16;i++){acc[i][0]=acc[i][1]=acc[i][2]=acc[i][3]=0.f;}

    float4 va[4], vb[4];
    load_stage(Atsrc, Hn, tid, va);
    load4(Bsrc, Dn, tid, vb);

    for (int kt=0; kt<32; ++kt){
        __syncthreads();
        store_stage(va, stg, tid);
        store_split(vb, sm, T1, T2, tid);
        if (kt < 31){
            load_stage(Atsrc + (size_t)(kt+1)*32*Hn, Hn, tid, va);
            load4(Bsrc + (kt+1)*32, Dn, tid, vb);
        }
        __syncthreads();
        trans_single(stg, sm, T0, tid);
        __syncthreads();
        mma_chunk_Bs(sb+T0, sb+T1, sb+T2, acc, lane, wm, wn);
    }

    const int qrow = lane>>2, qc = (lane&3)*2;
#pragma unroll
    for (int mi=0;mi<2;mi++){
        const int m = h0 + wm + mi*16 + qrow;
#pragma unroll
        for (int ni=0;ni<8;ni++){
            const int n = wn + ni*8 + qc;
            float* o0 = g_Tt + ((size_t)b*Hn + m)*Qn + n;
            const float* c = acc[mi*8+ni];
            *(float2*)o0          = make_float2(c[0], c[1]);
            *(float2*)(o0 + 8*Qn) = make_float2(c[2], c[3]);
        }
    }
}

// ---------------- K5a body: A_d2q = P @ Uq ; write segments 0,1,2 ----------------
__device__ __forceinline__ void k5a_body(char* sm, const float* __restrict__ Ud,
                                         const float* __restrict__ Uq,
                                         float* __restrict__ out, int i)
{
    float* stg = (float*)(sm + STG_OFF);
    const int tid = threadIdx.x, lane = tid&31, wid = tid>>5;
    const int b = i>>6, m0 = ((i>>3)&7)*128, h0 = (i&7)*128;
    const int wm = (wid&3)*32, wn = (wid>>2)*64;
    const uint32_t sb = smem_u32(sm);

    const float* Asrc  = g_P + ((size_t)b*Dn + m0)*Qn;   // [d][q]
    const float* Btsrc = Uq + (size_t)b*Qn*Hn + h0;      // rows q, cols h

    float acc[16][4];
#pragma unroll
    for (int i2=0;i2<16;i2++){acc[i2][0]=acc[i2][1]=acc[i2][2]=acc[i2][3]=0.f;}

    float4 va[4], vb[4];
    load4(Asrc, Qn, tid, va);
    load_stage(Btsrc, Hn, tid, vb);

    for (int kt=0; kt<4; ++kt){
        __syncthreads();
        store_split(va, sm, T0, T1, tid);
        store_stage(vb, stg, tid);
        if (kt < 3){
            load4(Asrc + (kt+1)*32, Qn, tid, va);
            load_stage(Btsrc + (size_t)(kt+1)*32*Hn, Hn, tid, vb);
        }
        __syncthreads();
        trans_single(stg, sm, T2, tid);
        __syncthreads();
        mma_chunk_As(sb+T0, sb+T1, sb+T2, acc, lane, wm, wn);
    }

    const int qrow = lane>>2, qc = (lane&3)*2;
#pragma unroll
    for (int mi=0;mi<2;mi++){
        const int m = m0 + wm + mi*16 + qrow;
#pragma unroll
        for (int ni=0;ni<8;ni++){
            const int h = h0 + wn + ni*8 + qc;
            const float* c = acc[mi*8+ni];
            const float2 u0 = *(const float2*)(Ud + ((size_t)b*Dn + m)*Hn + h);
            const float2 u1 = *(const float2*)(Ud + ((size_t)b*Dn + m + 8)*Hn + h);
            float* o0 = out + ((size_t)b*Dn + m)*(4*Hn) + h;
            float* o1 = o0 + (size_t)8*(4*Hn);
            *(float2*)(o0)        = u0;
            *(float2*)(o0 + Hn)   = make_float2(c[0], c[1]);
            *(float2*)(o0 + 2*Hn) = make_float2(u0.x*c[0], u0.y*c[1]);
            *(float2*)(o1)        = u1;
            *(float2*)(o1 + Hn)   = make_float2(c[2], c[3]);
            *(float2*)(o1 + 2*Hn) = make_float2(u1.x*c[2], u1.y*c[3]);
        }
    }
}

// ---------------- merged K4 + K5a launch ----------------
__global__ void __launch_bounds__(256)
k45(const float* __restrict__ Ud, const float* __restrict__ Uq, float* __restrict__ out)
{
    extern __shared__ __align__(16) char sm[];
    if (blockIdx.x < 128) k4_body(sm, Ud, blockIdx.x);
    else                  k5a_body(sm, Ud, Uq, out, blockIdx.x - 128);
}

// ---------------- K5b: A_q2d = P @ T ; write segment 3 ----------------
__global__ void __launch_bounds__(256)
k5b_out(const float* __restrict__ Ud, float* __restrict__ out)
{
    extern __shared__ __align__(16) char sm[];
    const int tid = threadIdx.x, lane = tid&31, wid = tid>>5;
    const int b = blockIdx.z, m0 = blockIdx.y*128, h0 = blockIdx.x*128;
    const int wm = (wid&3)*32, wn = (wid>>2)*64;
    const uint32_t sb = smem_u32(sm);

    const float* Asrc = g_P + ((size_t)b*Dn + m0)*Qn;    // [d][q]
    const float* Bsrc = g_Tt + ((size_t)b*Hn + h0)*Qn;   // [h][q]

    float acc[16][4];
#pragma unroll
    for (int i=0;i<16;i++){acc[i][0]=acc[i][1]=acc[i][2]=acc[i][3]=0.f;}

    float4 va[4], vb[4];
    load4(Asrc, Qn, tid, va);
    load4(Bsrc, Qn, tid, vb);

    for (int kt=0; kt<4; ++kt){
        __syncthreads();
        store_split(va, sm, T0, T1, tid);
        store_single(vb, sm, T2, tid);
        if (kt < 3){
            load4(Asrc + (kt+1)*32, Qn, tid, va);
            load4(Bsrc + (kt+1)*32, Qn, tid, vb);
        }
        __syncthreads();
        mma_chunk_As(sb+T0, sb+T1, sb+T2, acc, lane, wm, wn);
    }

    const int qrow = lane>>2, qc = (lane&3)*2;
#pragma unroll
    for (int mi=0;mi<2;mi++){
        const int m = m0 + wm + mi*16 + qrow;
#pragma unroll
        for (int ni=0;ni<8;ni++){
            const int h = h0 + wn + ni*8 + qc;
            const float* c = acc[mi*8+ni];
            const float2 u0 = *(const float2*)(Ud + ((size_t)b*Dn + m)*Hn + h);
            const float2 u1 = *(const float2*)(Ud + ((size_t)b*Dn + m + 8)*Hn + h);
            float* o0 = out + ((size_t)b*Dn + m)*(4*Hn) + 3*Hn + h;
            float* o1 = o0 + (size_t)8*(4*Hn);
            *(float2*)o0 = make_float2(u0.x*c[0], u0.y*c[1]);
            *(float2*)o1 = make_float2(u1.x*c[2], u1.y*c[3]);
        }
    }
}

// ---------------- launch ----------------
extern "C" void kernel_launch(void* const* d_in, const int* in_sizes, int n_in,
                              void* d_out, int out_size)
{
    const float* Ud    = (const float*)d_in[0];
    const float* Uq    = (const float*)d_in[1];
    const float* wc    = (const float*)d_in[2];
    const float* wcb   = (const float*)d_in[3];
    const int*   qmask = (const int*)d_in[4];
    const int*   dmask = (const int*)d_in[5];
    float* out = (float*)d_out;
    (void)in_sizes; (void)n_in; (void)out_size;

    const int nrows = Bn*Dn + Bn*Qn;
    k0_rowdots   <<<(nrows + 7)/8, 256>>>(Ud, Uq, wc);
    k1_score     <<<dim3(Dn/128, Bn), 256, SMEM_DIRECT>>>(Ud, Uq, wc, wcb, qmask, dmask);
    k3_colsoftmax<<<dim3(Qn/32, Bn), dim3(32, 32)>>>(qmask, dmask);
    k45          <<<128 + (Hn/128)*(Dn/128)*Bn, 256, SMEM_STAGED>>>(Ud, Uq, out);
    k5b_out      <<<dim3(Hn/128, Dn/128, Bn), 256, SMEM_DIRECT>>>(Ud, out);
}

// round 15
// speedup vs baseline: 1.4508x; 1.4508x over previous
#include <cuda_runtime.h>
#include <cuda_fp16.h>
#include <cstdint>

#define Bn 16
#define Dn 1024
#define Qn 128
#define Hn 1024
#define NEGINF (-1e30f)

// ---------------- scratch (device globals; no allocations) ----------------
__device__ float g_S  [Bn*Dn*Qn];   // raw scores [b][d][q]
__device__ float g_P  [Bn*Dn*Qn];   // S_d2q      [b][d][q]
__device__ float g_P2t[Bn*Qn*Dn];   // S_q2d^T    [b][q][d]
__device__ float g_Tt [Bn*Hn*Qn];   // T^T        [b][h][q]
__device__ float g_sd [Bn*Dn];
__device__ float g_sq [Bn*Qn];

// ---------------- helpers ----------------
__device__ __forceinline__ uint32_t smem_u32(const void* p){
    uint32_t a;
    asm("{ .reg .u64 t; cvta.to.shared.u64 t, %1; cvt.u32.u64 %0, t; }" : "=r"(a) : "l"(p));
    return a;
}
__device__ __forceinline__ void ldm4(uint32_t r[4], uint32_t addr){
    asm volatile("ldmatrix.sync.aligned.m8n8.x4.shared.b16 {%0,%1,%2,%3},[%4];"
        : "=r"(r[0]),"=r"(r[1]),"=r"(r[2]),"=r"(r[3]) : "r"(addr));
}
__device__ __forceinline__ void mmah(float c[4], const uint32_t a[4], uint32_t b0, uint32_t b1){
    asm volatile("mma.sync.aligned.m16n8k16.row.col.f32.f16.f16.f32 "
        "{%0,%1,%2,%3},{%4,%5,%6,%7},{%8,%9},{%0,%1,%2,%3};"
        : "+f"(c[0]),"+f"(c[1]),"+f"(c[2]),"+f"(c[3])
        : "r"(a[0]),"r"(a[1]),"r"(a[2]),"r"(a[3]),"r"(b0),"r"(b1));
}
__device__ __forceinline__ uint32_t pk2h(float x0, float x1){
    __half2 h = __floats2half2_rn(x0, x1);
    return *(uint32_t*)&h;
}
__device__ __forceinline__ void split2h(float x0, float x1, uint32_t& hi, uint32_t& lo){
    __half h0 = __float2half_rn(x0), h1 = __float2half_rn(x1);
    float r0 = x0 - __half2float(h0), r1 = x1 - __half2float(h1);
    hi = (uint32_t)__half_as_ushort(h0) | ((uint32_t)__half_as_ushort(h1)<<16);
    lo = (uint32_t)__half_as_ushort(__float2half_rn(r0)) |
         ((uint32_t)__half_as_ushort(__float2half_rn(r1))<<16);
}

// fp16 tiles: rows x 32 k, row stride 40 halves (80 B)
// A tile: 128 rows (10240 B). B tile: 64 rows (5120 B).

// ---- A-tile (128x32) loaders: 256 thr, 16 floats each ----
__device__ __forceinline__ void loadA(const float* src, size_t ld, int tid, float4 v[4]){
    const float* p = src + (size_t)(tid>>1)*ld + (tid&1)*16;
#pragma unroll
    for (int j=0;j<4;j++) v[j] = *(const float4*)(p + j*4);
}
__device__ __forceinline__ void storeA_split(const float4 v[4], char* sm, int hiOff, int loOff, int tid){
    uint32_t h[8], l[8];
#pragma unroll
    for (int j=0;j<4;j++){
        split2h(v[j].x,v[j].y,h[2*j],l[2*j]);
        split2h(v[j].z,v[j].w,h[2*j+1],l[2*j+1]);
    }
    const int off = (tid>>1)*80 + (tid&1)*32;
    *(uint4*)(sm + hiOff + off)      = make_uint4(h[0],h[1],h[2],h[3]);
    *(uint4*)(sm + hiOff + off + 16) = make_uint4(h[4],h[5],h[6],h[7]);
    *(uint4*)(sm + loOff + off)      = make_uint4(l[0],l[1],l[2],l[3]);
    *(uint4*)(sm + loOff + off + 16) = make_uint4(l[4],l[5],l[6],l[7]);
}
// ---- B-tile (64x32) loaders: 256 thr, 8 floats each ----
__device__ __forceinline__ void loadB(const float* src, size_t ld, int tid, float4 v[2]){
    const float* p = src + (size_t)(tid>>2)*ld + (tid&3)*8;
    v[0] = *(const float4*)p; v[1] = *(const float4*)(p + 4);
}
__device__ __forceinline__ void storeB_single(const float4 v[2], char* sm, int off0, int tid){
    uint4 h = make_uint4(pk2h(v[0].x,v[0].y), pk2h(v[0].z,v[0].w),
                         pk2h(v[1].x,v[1].y), pk2h(v[1].z,v[1].w));
    *(uint4*)(sm + off0 + (tid>>2)*80 + (tid&3)*16) = h;
}
__device__ __forceinline__ void storeB_split(const float4 v[2], char* sm, int hiOff, int loOff, int tid){
    uint32_t h[4], l[4];
    split2h(v[0].x,v[0].y,h[0],l[0]); split2h(v[0].z,v[0].w,h[1],l[1]);
    split2h(v[1].x,v[1].y,h[2],l[2]); split2h(v[1].z,v[1].w,h[3],l[3]);
    const int off = (tid>>2)*80 + (tid&3)*16;
    *(uint4*)(sm + hiOff + off) = make_uint4(h[0],h[1],h[2],h[3]);
    *(uint4*)(sm + loOff + off) = make_uint4(l[0],l[1],l[2],l[3]);
}
// ---- staged transpose, 128-col source (k4 A): stg [32][132] fp32 ----
__device__ __forceinline__ void load_stage128(const float* src, size_t ld, int tid, float4 v[4]){
#pragma unroll
    for (int p=0;p<4;p++){
        const int idx = p*256 + tid;
        v[p] = *(const float4*)(src + (size_t)(idx>>5)*ld + (idx&31)*4);
    }
}
__device__ __forceinline__ void store_stage128(const float4 v[4], float* stg, int tid){
#pragma unroll
    for (int p=0;p<4;p++){
        const int idx = p*256 + tid;
        *(float4*)(stg + (idx>>5)*132 + (idx&31)*4) = v[p];
    }
}
__device__ __forceinline__ void trans128_single(const float* stg, char* sm, int off0, int tid){
    const int h = tid>>1, kb = (tid&1)*16;
#pragma unroll
    for (int j=0;j<8;j++){
        const int k = kb + 2*j;
        *(uint32_t*)(sm + off0 + h*80 + k*2) = pk2h(stg[k*132 + h], stg[(k+1)*132 + h]);
    }
}
// ---- staged transpose, 64-col source (k5a B): stg [32][68] fp32 ----
__device__ __forceinline__ void load_stage64(const float* src, size_t ld, int tid, float4 v[2]){
#pragma unroll
    for (int p=0;p<2;p++){
        const int idx = p*256 + tid;
        v[p] = *(const float4*)(src + (size_t)(idx>>4)*ld + (idx&15)*4);
    }
}
__device__ __forceinline__ void store_stage64(const float4 v[2], float* stg, int tid){
#pragma unroll
    for (int p=0;p<2;p++){
        const int idx = p*256 + tid;
        *(float4*)(stg + (idx>>4)*68 + (idx&15)*4) = v[p];
    }
}
__device__ __forceinline__ void trans64_single(const float* stg, char* sm, int off0, int tid){
    const int h = tid>>2, kb = (tid&3)*8;
#pragma unroll
    for (int j=0;j<4;j++){
        const int k = kb + 2*j;
        *(uint32_t*)(sm + off0 + h*80 + k*2) = pk2h(stg[k*68 + h], stg[(k+1)*68 + h]);
    }
}

// ---- 2-pass MMA over one 32-k chunk. warp tile 32m x 32n, 8 warps -> 128x64 ----
__device__ __forceinline__ void mma_As(uint32_t AH, uint32_t AL, uint32_t B,
                                       float acc[8][4], int lane, int wm, int wn)
{
    const int r16 = lane & 15;
    const int c8  = (lane >> 4) * 8;
#pragma unroll
    for (int kk = 0; kk < 32; kk += 16){
        uint32_t Ah[2][4], Al[2][4];
#pragma unroll
        for (int mi = 0; mi < 2; ++mi){
            const uint32_t off = (uint32_t)((wm + mi*16 + r16)*80 + (kk + c8)*2);
            ldm4(Ah[mi], AH + off);
            ldm4(Al[mi], AL + off);
        }
#pragma unroll
        for (int g = 0; g < 2; ++g){
            uint32_t b[4];
            ldm4(b, B + (uint32_t)((wn + g*16 + r16)*80 + (kk + c8)*2));
#pragma unroll
            for (int mi = 0; mi < 2; ++mi){
                mmah(acc[mi*4+2*g],   Ah[mi], b[0], b[2]);
                mmah(acc[mi*4+2*g+1], Ah[mi], b[1], b[3]);
                mmah(acc[mi*4+2*g],   Al[mi], b[0], b[2]);
                mmah(acc[mi*4+2*g+1], Al[mi], b[1], b[3]);
            }
        }
    }
}
__device__ __forceinline__ void mma_Bs(uint32_t A, uint32_t BH, uint32_t BL,
                                       float acc[8][4], int lane, int wm, int wn)
{
    const int r16 = lane & 15;
    const int c8  = (lane >> 4) * 8;
#pragma unroll
    for (int kk = 0; kk < 32; kk += 16){
        uint32_t Aa[2][4];
#pragma unroll
        for (int mi = 0; mi < 2; ++mi)
            ldm4(Aa[mi], A + (uint32_t)((wm + mi*16 + r16)*80 + (kk + c8)*2));
#pragma unroll
        for (int g = 0; g < 2; ++g){
            const uint32_t off = (uint32_t)((wn + g*16 + r16)*80 + (kk + c8)*2);
            uint32_t bh[4], bl[4];
            ldm4(bh, BH + off);
            ldm4(bl, BL + off);
#pragma unroll
            for (int mi = 0; mi < 2; ++mi){
                mmah(acc[mi*4+2*g],   Aa[mi], bh[0], bh[2]);
                mmah(acc[mi*4+2*g+1], Aa[mi], bh[1], bh[3]);
                mmah(acc[mi*4+2*g],   Aa[mi], bl[0], bl[2]);
                mmah(acc[mi*4+2*g+1], Aa[mi], bl[1], bl[3]);
            }
        }
    }
}

// ---------------- K0: s_d and s_q row dots ----------------
__global__ void k0_rowdots(const float* __restrict__ Ud, const float* __restrict__ Uq,
                           const float* __restrict__ wc)
{
    const int warp = (blockIdx.x * blockDim.x + threadIdx.x) >> 5;
    const int lane = threadIdx.x & 31;
    const int nrows = Bn*Dn + Bn*Qn;
    if (warp >= nrows) return;
    const float* row; const float* w; float* outp;
    if (warp < Bn*Dn) { row = Ud + (size_t)warp * Hn; w = wc;      outp = &g_sd[warp]; }
    else { int r = warp - Bn*Dn; row = Uq + (size_t)r * Hn; w = wc + Hn; outp = &g_sq[r]; }
    float s = 0.f;
#pragma unroll
    for (int j = 0; j < Hn/128; ++j) {
        float4 a  = *(const float4*)(row + (j*32 + lane)*4);
        float4 ww = *(const float4*)(w   + (j*32 + lane)*4);
        s += a.x*ww.x + a.y*ww.y + a.z*ww.z + a.w*ww.w;
    }
#pragma unroll
    for (int o = 16; o; o >>= 1) s += __shfl_xor_sync(0xffffffffu, s, o);
    if (lane == 0) *outp = s;
}

// ---------------- K1: S = (Ud*w)@Uq^T + s_d + s_q + b ----------------
// grid (16, 16): bx -> (mtile = bx>>1, qtile = bx&1). CTA 128m x 64q, K=1024.
#define K1_SMEM (10240+10240+5120)
__global__ void __launch_bounds__(256, 2)
k1_score(const float* __restrict__ Ud, const float* __restrict__ Uq,
         const float* __restrict__ wc, const float* __restrict__ wcb)
{
    extern __shared__ __align__(16) char sm[];
    const int tid = threadIdx.x, lane = tid&31, wid = tid>>5;
    const int b = blockIdx.y, m0 = (blockIdx.x>>1)*128, n0 = (blockIdx.x&1)*64;
    const int wm = (wid&3)*32, wn = (wid>>2)*32;
    const uint32_t sb = smem_u32(sm);
    const int AH = 0, AL = 10240, BT = 20480;

    const float* Asrc = Ud + ((size_t)b*Dn + m0)*Hn;
    const float* Bsrc = Uq + ((size_t)b*Qn + n0)*Hn;
    const float* wd = wc + 2*Hn;

    float acc[8][4];
#pragma unroll
    for (int i=0;i<8;i++){acc[i][0]=acc[i][1]=acc[i][2]=acc[i][3]=0.f;}

    float4 va[4], vb[2];
    loadA(Asrc, Hn, tid, va);
    {   const float* wp = wd + (tid&1)*16;
#pragma unroll
        for (int j=0;j<4;j++){ float4 w=*(const float4*)(wp+j*4); va[j].x*=w.x; va[j].y*=w.y; va[j].z*=w.z; va[j].w*=w.w; } }
    loadB(Bsrc, Hn, tid, vb);

    for (int kt=0; kt<32; ++kt){
        __syncthreads();
        storeA_split(va, sm, AH, AL, tid);
        storeB_single(vb, sm, BT, tid);
        if (kt < 31){
            loadA(Asrc + (kt+1)*32, Hn, tid, va);
            const float* wp = wd + (kt+1)*32 + (tid&1)*16;
#pragma unroll
            for (int j=0;j<4;j++){ float4 w=*(const float4*)(wp+j*4); va[j].x*=w.x; va[j].y*=w.y; va[j].z*=w.z; va[j].w*=w.w; }
            loadB(Bsrc + (kt+1)*32, Hn, tid, vb);
        }
        __syncthreads();
        mma_As(sb+AH, sb+AL, sb+BT, acc, lane, wm, wn);
    }

    const float bias = wcb[0];
    const int qrow = lane>>2, qc = (lane&3)*2;
#pragma unroll
    for (int mi=0;mi<2;mi++){
        const int m = m0 + wm + mi*16 + qrow;
        const float sd0 = g_sd[b*Dn + m] + bias;
        const float sd1 = g_sd[b*Dn + m + 8] + bias;
#pragma unroll
        for (int ni=0;ni<4;ni++){
            const int q = n0 + wn + ni*8 + qc;
            const float2 sq = *(const float2*)(g_sq + b*Qn + q);
            float* o0 = g_S + ((size_t)b*Dn + m)*Qn + q;
            const float* c = acc[mi*4+ni];
            *(float2*)o0          = make_float2(c[0]+sd0+sq.x, c[1]+sd0+sq.y);
            *(float2*)(o0 + 8*Qn) = make_float2(c[2]+sd1+sq.x, c[3]+sd1+sq.y);
        }
    }
}

// ---------------- K2: row softmax over q -> g_P ----------------
__global__ void k2_rowsoftmax(const int* __restrict__ qmask, const int* __restrict__ dmask)
{
    const int row  = (blockIdx.x * blockDim.x + threadIdx.x) >> 5;
    const int lane = threadIdx.x & 31;
    if (row >= Bn*Dn) return;
    const int b = row >> 10;
    const float4 s = *(const float4*)(g_S + (size_t)row*Qn + lane*4);
    const int dm = dmask[row];
    const int4 qm = *(const int4*)(qmask + b*Qn + lane*4);
    const bool m0v = (dm > 0) && (qm.x > 0);
    const bool m1v = (dm > 0) && (qm.y > 0);
    const bool m2v = (dm > 0) && (qm.z > 0);
    const bool m3v = (dm > 0) && (qm.w > 0);
    const float l0 = m0v ? s.x : NEGINF;
    const float l1 = m1v ? s.y : NEGINF;
    const float l2 = m2v ? s.z : NEGINF;
    const float l3 = m3v ? s.w : NEGINF;
    float mx = fmaxf(fmaxf(l0, l1), fmaxf(l2, l3));
#pragma unroll
    for (int o = 16; o; o >>= 1) mx = fmaxf(mx, __shfl_xor_sync(0xffffffffu, mx, o));
    const float e0 = __expf(l0 - mx), e1 = __expf(l1 - mx);
    const float e2 = __expf(l2 - mx), e3 = __expf(l3 - mx);
    float sme = e0 + e1 + e2 + e3;
#pragma unroll
    for (int o = 16; o; o >>= 1) sme += __shfl_xor_sync(0xffffffffu, sme, o);
    const float inv = 1.f / sme;
    *(float4*)(g_P + (size_t)row*Qn + lane*4) =
        make_float4(m0v ? e0*inv : 0.f, m1v ? e1*inv : 0.f, m2v ? e2*inv : 0.f, m3v ? e3*inv : 0.f);
}

// ---------------- K3: column softmax over d -> g_P2t (transposed out) ----------------
__global__ void __launch_bounds__(1024)
k3_colsoftmax(const int* __restrict__ qmask, const int* __restrict__ dmask)
{
    const int b  = blockIdx.y;
    const int tx = threadIdx.x, ty = threadIdx.y;
    const int q0 = blockIdx.x*32;
    const int q  = q0 + tx;
    __shared__ float red[32][33];
    __shared__ float trn[32][33];
    const int qm = qmask[b*Qn + q];
    float v[32];
    float mx = -3.0e38f;
#pragma unroll
    for (int j = 0; j < 32; ++j) {
        const int d = ty + j*32;
        const float s = g_S[((size_t)b*Dn + d)*Qn + q];
        const float l = (qm > 0 && dmask[b*Dn + d] > 0) ? s : NEGINF;
        v[j] = l; mx = fmaxf(mx, l);
    }
    red[ty][tx] = mx; __syncthreads();
#pragma unroll
    for (int off = 16; off; off >>= 1) {
        if (ty < off) red[ty][tx] = fmaxf(red[ty][tx], red[ty+off][tx]);
        __syncthreads();
    }
    mx = red[0][tx];
    __syncthreads();
    float se = 0.f;
#pragma unroll
    for (int j = 0; j < 32; ++j) { v[j] = __expf(v[j] - mx); se += v[j]; }
    red[ty][tx] = se; __syncthreads();
#pragma unroll
    for (int off = 16; off; off >>= 1) {
        if (ty < off) red[ty][tx] += red[ty+off][tx];
        __syncthreads();
    }
    const float inv = 1.f / red[0][tx];
    __syncthreads();
    for (int j = 0; j < 32; ++j) {
        const int d = ty + j*32;
        const float ind = (qm > 0 && dmask[b*Dn + d] > 0) ? 1.f : 0.f;
        trn[ty][tx] = v[j]*inv*ind;
        __syncthreads();
        g_P2t[((size_t)b*Qn + q0 + ty)*Dn + j*32 + tx] = trn[tx][ty];
        __syncthreads();
    }
}

// ---------------- K4: T^T[h][q] = sum_d Ud^T[h][d] * P2t[q][d] ----------------
// grid (16, 16): bx -> (htile = bx>>1, qtile = bx&1). CTA 128h x 64q, K=1024.
#define K4_SMEM (10240+5120+5120 + 16896)
__global__ void __launch_bounds__(256, 2)
k4_T(const float* __restrict__ Ud)
{
    extern __shared__ __align__(16) char sm[];
    const int A0 = 0, BH = 10240, BL = 15360, SG = 20480;
    float* stg = (float*)(sm + SG);
    const int tid = threadIdx.x, lane = tid&31, wid = tid>>5;
    const int b = blockIdx.y, h0 = (blockIdx.x>>1)*128, q0 = (blockIdx.x&1)*64;
    const int wm = (wid&3)*32, wn = (wid>>2)*32;
    const uint32_t sb = smem_u32(sm);

    const float* Atsrc = Ud + (size_t)b*Dn*Hn + h0;          // [d][h]
    const float* Bsrc  = g_P2t + ((size_t)b*Qn + q0)*Dn;     // [q][d]

    float acc[8][4];
#pragma unroll
    for (int i=0;i<8;i++){acc[i][0]=acc[i][1]=acc[i][2]=acc[i][3]=0.f;}

    float4 va[4], vb[2];
    load_stage128(Atsrc, Hn, tid, va);
    loadB(Bsrc, Dn, tid, vb);

    for (int kt=0; kt<32; ++kt){
        __syncthreads();
        store_stage128(va, stg, tid);
        storeB_split(vb, sm, BH, BL, tid);
        if (kt < 31){
            load_stage128(Atsrc + (size_t)(kt+1)*32*Hn, Hn, tid, va);
            loadB(Bsrc + (kt+1)*32, Dn, tid, vb);
        }
        __syncthreads();
        trans128_single(stg, sm, A0, tid);
        __syncthreads();
        mma_Bs(sb+A0, sb+BH, sb+BL, acc, lane, wm, wn);
    }

    const int qrow = lane>>2, qc = (lane&3)*2;
#pragma unroll
    for (int mi=0;mi<2;mi++){
        const int m = h0 + wm + mi*16 + qrow;
#pragma unroll
        for (int ni=0;ni<4;ni++){
            const int n = q0 + wn + ni*8 + qc;
            float* o0 = g_Tt + ((size_t)b*Hn + m)*Qn + n;
            const float* c = acc[mi*4+ni];
            *(float2*)o0          = make_float2(c[0], c[1]);
            *(float2*)(o0 + 8*Qn) = make_float2(c[2], c[3]);
        }
    }
}

// ---------------- K5a: A_d2q = P @ Uq ; write segments 0,1,2 ----------------
// grid (16, 8, 16): bx h-tile(64), by m-tile(128), bz b. K=128.
#define K5A_SMEM (10240+10240+5120 + 8704)
__global__ void __launch_bounds__(256, 2)
k5a_out(const float* __restrict__ Ud, const float* __restrict__ Uq,
        float* __restrict__ out)
{
    extern __shared__ __align__(16) char sm[];
    const int AH = 0, AL = 10240, BT = 20480, SG = 25600;
    float* stg = (float*)(sm + SG);
    const int tid = threadIdx.x, lane = tid&31, wid = tid>>5;
    const int b = blockIdx.z, m0 = blockIdx.y*128, h0 = blockIdx.x*64;
    const int wm = (wid&3)*32, wn = (wid>>2)*32;
    const uint32_t sb = smem_u32(sm);

    const float* Asrc  = g_P + ((size_t)b*Dn + m0)*Qn;   // [d][q]
    const float* Btsrc = Uq + (size_t)b*Qn*Hn + h0;      // [q][h]

    float acc[8][4];
#pragma unroll
    for (int i=0;i<8;i++){acc[i][0]=acc[i][1]=acc[i][2]=acc[i][3]=0.f;}

    float4 va[4], vb[2];
    loadA(Asrc, Qn, tid, va);
    load_stage64(Btsrc, Hn, tid, vb);

    for (int kt=0; kt<4; ++kt){
        __syncthreads();
        storeA_split(va, sm, AH, AL, tid);
        store_stage64(vb, stg, tid);
        if (kt < 3){
            loadA(Asrc + (kt+1)*32, Qn, tid, va);
            load_stage64(Btsrc + (size_t)(kt+1)*32*Hn, Hn, tid, vb);
        }
        __syncthreads();
        trans64_single(stg, sm, BT, tid);
        __syncthreads();
        mma_As(sb+AH, sb+AL, sb+BT, acc, lane, wm, wn);
    }

    const int qrow = lane>>2, qc = (lane&3)*2;
#pragma unroll
    for (int mi=0;mi<2;mi++){
        const int m = m0 + wm + mi*16 + qrow;
#pragma unroll
        for (int ni=0;ni<4;ni++){
            const int h = h0 + wn + ni*8 + qc;
            const float* c = acc[mi*4+ni];
            const float2 u0 = *(const float2*)(Ud + ((size_t)b*Dn + m)*Hn + h);
            const float2 u1 = *(const float2*)(Ud + ((size_t)b*Dn + m + 8)*Hn + h);
            float* o0 = out + ((size_t)b*Dn + m)*(4*Hn) + h;
            float* o1 = o0 + (size_t)8*(4*Hn);
            *(float2*)(o0)        = u0;
            *(float2*)(o0 + Hn)   = make_float2(c[0], c[1]);
            *(float2*)(o0 + 2*Hn) = make_float2(u0.x*c[0], u0.y*c[1]);
            *(float2*)(o1)        = u1;
            *(float2*)(o1 + Hn)   = make_float2(c[2], c[3]);
            *(float2*)(o1 + 2*Hn) = make_float2(u1.x*c[2], u1.y*c[3]);
        }
    }
}

// ---------------- K5b: A_q2d = P @ T ; write segment 3 ----------------
// grid (16, 8, 16). B = Tt direct K-major. K=128.
#define K5B_SMEM (10240+10240+5120)
__global__ void __launch_bounds__(256, 2)
k5b_out(const float* __restrict__ Ud, float* __restrict__ out)
{
    extern __shared__ __align__(16) char sm[];
    const int AH = 0, AL = 10240, BT = 20480;
    const int tid = threadIdx.x, lane = tid&31, wid = tid>>5;
    const int b = blockIdx.z, m0 = blockIdx.y*128, h0 = blockIdx.x*64;
    const int wm = (wid&3)*32, wn = (wid>>2)*32;
    const uint32_t sb = smem_u32(sm);

    const float* Asrc = g_P + ((size_t)b*Dn + m0)*Qn;    // [d][q]
    const float* Bsrc = g_Tt + ((size_t)b*Hn + h0)*Qn;   // [h][q]

    float acc[8][4];
#pragma unroll
    for (int i=0;i<8;i++){acc[i][0]=acc[i][1]=acc[i][2]=acc[i][3]=0.f;}

    float4 va[4], vb[2];
    loadA(Asrc, Qn, tid, va);
    loadB(Bsrc, Qn, tid, vb);

    for (int kt=0; kt<4; ++kt){
        __syncthreads();
        storeA_split(va, sm, AH, AL, tid);
        storeB_single(vb, sm, BT, tid);
        if (kt < 3){
            loadA(Asrc + (kt+1)*32, Qn, tid, va);
            loadB(Bsrc + (kt+1)*32, Qn, tid, vb);
        }
        __syncthreads();
        mma_As(sb+AH, sb+AL, sb+BT, acc, lane, wm, wn);
    }

    const int qrow = lane>>2, qc = (lane&3)*2;
#pragma unroll
    for (int mi=0;mi<2;mi++){
        const int m = m0 + wm + mi*16 + qrow;
#pragma unroll
        for (int ni=0;ni<4;ni++){
            const int h = h0 + wn + ni*8 + qc;
            const float* c = acc[mi*4+ni];
            const float2 u0 = *(const float2*)(Ud + ((size_t)b*Dn + m)*Hn + h);
            const float2 u1 = *(const float2*)(Ud + ((size_t)b*Dn + m + 8)*Hn + h);
            float* o0 = out + ((size_t)b*Dn + m)*(4*Hn) + 3*Hn + h;
            float* o1 = o0 + (size_t)8*(4*Hn);
            *(float2*)o0 = make_float2(u0.x*c[0], u0.y*c[1]);
            *(float2*)o1 = make_float2(u1.x*c[2], u1.y*c[3]);
        }
    }
}

// ---------------- launch ----------------
extern "C" void kernel_launch(void* const* d_in, const int* in_sizes, int n_in,
                              void* d_out, int out_size)
{
    const float* Ud    = (const float*)d_in[0];
    const float* Uq    = (const float*)d_in[1];
    const float* wc    = (const float*)d_in[2];
    const float* wcb   = (const float*)d_in[3];
    const int*   qmask = (const int*)d_in[4];
    const int*   dmask = (const int*)d_in[5];
    float* out = (float*)d_out;
    (void)in_sizes; (void)n_in; (void)out_size;

    const int nrows = Bn*Dn + Bn*Qn;
    k0_rowdots   <<<(nrows + 7)/8, 256>>>(Ud, Uq, wc);
    k1_score     <<<dim3(16, Bn), 256, K1_SMEM>>>(Ud, Uq, wc, wcb);
    k2_rowsoftmax<<<(Bn*Dn)/8, 256>>>(qmask, dmask);
    k3_colsoftmax<<<dim3(Qn/32, Bn), dim3(32, 32)>>>(qmask, dmask);
    k4_T         <<<dim3(16, Bn), 256, K4_SMEM>>>(Ud);
    k5a_out      <<<dim3(Hn/64, Dn/128, Bn), 256, K5A_SMEM>>>(Ud, Uq, out);
    k5b_out      <<<dim3(Hn/64, Dn/128, Bn), 256, K5B_SMEM>>>(Ud, out);
}